// round 1
// baseline (speedup 1.0000x reference)
#include <cuda_runtime.h>
#include <cstdint>

#define BEV_H 128
#define BEV_W 128
#define HW_ (BEV_H * BEV_W)
#define C_MID 80
#define C_OUT 128
#define B_ 4
#define NP_ 200000
#define TOTAL_PTS (B_ * NP_)

// Scratch (device globals -- no allocation allowed)
__device__ float g_sums[(size_t)B_ * HW_ * C_MID];  // ~21 MB
__device__ float g_cnt[B_ * HW_];

// ---------------------------------------------------------------------------
// Kernel 0: zero the scratch accumulators (graph replays require re-zeroing)
// ---------------------------------------------------------------------------
__global__ void zero_kernel() {
    const int stride = gridDim.x * blockDim.x;
    const int total_s = B_ * HW_ * C_MID;
    for (int i = blockIdx.x * blockDim.x + threadIdx.x; i < total_s; i += stride)
        g_sums[i] = 0.0f;
    const int total_c = B_ * HW_;
    for (int i = blockIdx.x * blockDim.x + threadIdx.x; i < total_c; i += stride)
        g_cnt[i] = 0.0f;
}

// ---------------------------------------------------------------------------
// Kernel 1: per-point MLP (4->80 relu, 80->80 relu) + scatter-add into BEV
// One thread = one point. W1/W2/biases staged in shared, broadcast reads.
// ---------------------------------------------------------------------------
__global__ __launch_bounds__(256)
void point_kernel(const float4* __restrict__ pts,
                  const float* __restrict__ W1, const float* __restrict__ b1,
                  const float* __restrict__ W2, const float* __restrict__ b2) {
    __shared__ float sW1[4 * C_MID];
    __shared__ float sb1[C_MID];
    __shared__ float sb2[C_MID];
    __shared__ float sW2[C_MID * C_MID];

    for (int i = threadIdx.x; i < 4 * C_MID; i += 256) sW1[i] = W1[i];
    for (int i = threadIdx.x; i < C_MID; i += 256) { sb1[i] = b1[i]; sb2[i] = b2[i]; }
    for (int i = threadIdx.x; i < C_MID * C_MID; i += 256) sW2[i] = W2[i];
    __syncthreads();

    const int stride = gridDim.x * 256;
    for (int i = blockIdx.x * 256 + threadIdx.x; i < TOTAL_PTS; i += stride) {
        float4 p = pts[i];

        // Bucket index. Match reference fp32 arithmetic: floor((x - xmin)/mx).
        int ix = (int)floorf((p.x + 50.0f) / 0.78125f);
        int iy = (int)floorf((p.y + 50.0f) / 0.78125f);
        bool valid = (ix >= 0) & (ix < BEV_W) & (iy >= 0) & (iy < BEV_H);
        if (!valid) continue;  // reference routes these to a discarded dummy bucket

        int b = i / NP_;
        int g = b * HW_ + iy * BEV_W + ix;

        // Layer 1: h = relu(p @ W1 + b1), W1 is (4, 80) row-major
        float h[C_MID];
#pragma unroll
        for (int c = 0; c < C_MID; c++) {
            float v = sb1[c];
            v = fmaf(p.x, sW1[c], v);
            v = fmaf(p.y, sW1[C_MID + c], v);
            v = fmaf(p.z, sW1[2 * C_MID + c], v);
            v = fmaf(p.w, sW1[3 * C_MID + c], v);
            h[c] = fmaxf(v, 0.0f);
        }

        // Layer 2: emb = relu(h @ W2 + b2), scatter-add immediately
        float* sums = &g_sums[(size_t)g * C_MID];
#pragma unroll 2
        for (int d = 0; d < C_MID; d++) {
            float acc = sb2[d];
#pragma unroll
            for (int c = 0; c < C_MID; c++)
                acc = fmaf(h[c], sW2[c * C_MID + d], acc);
            atomicAdd(&sums[d], fmaxf(acc, 0.0f));
        }
        atomicAdd(&g_cnt[g], 1.0f);
    }
}

// ---------------------------------------------------------------------------
// Kernel 2: mean + 1x1 conv (80->128) + BN + relu, NCHW output.
// One block per (b, iy) row, one thread per ix. Coalesced output stores.
// ---------------------------------------------------------------------------
#define SUM_PAD 81  // conflict-free shared stride (gcd(81*? ,32) trick: 81*4B -> stride 17 banks)

__global__ __launch_bounds__(128)
void bev_kernel(const float* __restrict__ Wp, const float* __restrict__ bp,
                const float* __restrict__ gamma, const float* __restrict__ beta,
                const float* __restrict__ rmean, const float* __restrict__ rvar,
                float* __restrict__ out) {
    extern __shared__ float smem[];
    float* sWp    = smem;                          // 80*128
    float* sSum   = sWp + C_MID * C_OUT;           // 128*81
    float* sScale = sSum + 128 * SUM_PAD;          // 128
    float* sShift = sScale + C_OUT;                // 128

    const int tid = threadIdx.x;
    const int row = blockIdx.x;            // row = b*128 + iy; bucket = row*128 + ix

    for (int i = tid; i < C_MID * C_OUT; i += 128) sWp[i] = Wp[i];
    if (tid < C_OUT) {
        float sc = gamma[tid] * rsqrtf(rvar[tid] + 1e-5f);
        sScale[tid] = sc;
        sShift[tid] = beta[tid] + (bp[tid] - rmean[tid]) * sc;
    }
    // Stage this row's 128 buckets x 80 sums, coalesced from global.
    const size_t gbase = (size_t)row * 128 * C_MID;
    for (int i = tid; i < 128 * C_MID; i += 128) {
        int px = i / C_MID, c = i % C_MID;
        sSum[px * SUM_PAD + c] = g_sums[gbase + i];
    }
    __syncthreads();

    float cnt = g_cnt[row * 128 + tid];
    float inv = 1.0f / fmaxf(cnt, 1.0f);
    float m[C_MID];
#pragma unroll
    for (int c = 0; c < C_MID; c++) m[c] = sSum[tid * SUM_PAD + c] * inv;

    const int b = row / BEV_H;
    const int iy = row % BEV_H;
    float* outp = out + (size_t)b * C_OUT * HW_ + (size_t)iy * BEV_W + tid;

#pragma unroll 2
    for (int d = 0; d < C_OUT; d++) {
        float acc = 0.0f;
#pragma unroll
        for (int c = 0; c < C_MID; c++)
            acc = fmaf(m[c], sWp[c * C_OUT + d], acc);
        outp[(size_t)d * HW_] = fmaxf(fmaf(acc, sScale[d], sShift[d]), 0.0f);
    }
}

// ---------------------------------------------------------------------------
extern "C" void kernel_launch(void* const* d_in, const int* in_sizes, int n_in,
                              void* d_out, int out_size) {
    const float4* pts   = (const float4*)d_in[0];
    const float*  W1    = (const float*)d_in[1];
    const float*  b1    = (const float*)d_in[2];
    const float*  W2    = (const float*)d_in[3];
    const float*  b2    = (const float*)d_in[4];
    const float*  Wp    = (const float*)d_in[5];
    const float*  bp    = (const float*)d_in[6];
    const float*  gamma = (const float*)d_in[7];
    const float*  beta  = (const float*)d_in[8];
    const float*  rmean = (const float*)d_in[9];
    const float*  rvar  = (const float*)d_in[10];
    float* out = (float*)d_out;

    zero_kernel<<<2048, 256>>>();

    int blocks = (TOTAL_PTS + 255) / 256;
    point_kernel<<<blocks, 256>>>(pts, W1, b1, W2, b2);

    size_t smem = (C_MID * C_OUT + 128 * SUM_PAD + 2 * C_OUT) * sizeof(float);
    cudaFuncSetAttribute(bev_kernel, cudaFuncAttributeMaxDynamicSharedMemorySize, (int)smem);
    bev_kernel<<<B_ * BEV_H, 128, smem>>>(Wp, bp, gamma, beta, rmean, rvar, out);
}

// round 2
// speedup vs baseline: 1.1579x; 1.1579x over previous
#include <cuda_runtime.h>
#include <cstdint>

#define BEV_H 128
#define BEV_W 128
#define HW_ (BEV_H * BEV_W)
#define C_MID 80
#define C_OUT 128
#define B_ 4
#define NP_ 200000
#define TOTAL_PTS (B_ * NP_)

// Scratch (device globals -- no allocation allowed)
__device__ float g_sums[(size_t)B_ * HW_ * C_MID];  // ~21 MB
__device__ float g_cnt[B_ * HW_];

// ---------------------------------------------------------------------------
// Packed fp32x2 helpers (sm_103a; ptxas never auto-fuses these)
// ---------------------------------------------------------------------------
__device__ __forceinline__ void fma2(double& acc, double a, double b) {
    asm("fma.rn.f32x2 %0, %1, %2, %3;" : "=d"(acc) : "d"(a), "d"(b), "d"(acc));
}
__device__ __forceinline__ double add2(double a, double b) {
    double r;
    asm("add.rn.f32x2 %0, %1, %2;" : "=d"(r) : "d"(a), "d"(b));
    return r;
}
__device__ __forceinline__ double pack2(float lo, float hi) {
    double r;
    asm("mov.b64 %0, {%1, %2};" : "=d"(r) : "f"(lo), "f"(hi));
    return r;
}
__device__ __forceinline__ float2 unpack2(double a) {
    float lo, hi;
    asm("mov.b64 {%0, %1}, %2;" : "=f"(lo), "=f"(hi) : "d"(a));
    return make_float2(lo, hi);
}

// ---------------------------------------------------------------------------
// Kernel 0: zero scratch accumulators (graph replays require re-zeroing)
// ---------------------------------------------------------------------------
__global__ void zero_kernel() {
    const int stride = gridDim.x * blockDim.x;
    const int total_s = B_ * HW_ * C_MID;
    for (int i = blockIdx.x * blockDim.x + threadIdx.x; i < total_s; i += stride)
        g_sums[i] = 0.0f;
    const int total_c = B_ * HW_;
    for (int i = blockIdx.x * blockDim.x + threadIdx.x; i < total_c; i += stride)
        g_cnt[i] = 0.0f;
}

// ---------------------------------------------------------------------------
// Kernel 1: per-point MLP + scatter. One thread = one point.
// Layer 2 done 2-wide: h packed over (c, c+1), W2 staged transposed so one
// broadcast LDS.128 feeds two fma.rn.f32x2. Scatter via red.global.add.v4.f32.
// ---------------------------------------------------------------------------
__global__ __launch_bounds__(256, 2)
void point_kernel(const float4* __restrict__ pts,
                  const float* __restrict__ W1, const float* __restrict__ b1,
                  const float* __restrict__ W2, const float* __restrict__ b2) {
    __shared__ float sW1[4 * C_MID];
    __shared__ float sb1[C_MID];
    __shared__ float sb2[C_MID];
    __shared__ __align__(16) float sW2T[C_MID * C_MID];  // [d][c]

    for (int i = threadIdx.x; i < 4 * C_MID; i += 256) sW1[i] = W1[i];
    for (int i = threadIdx.x; i < C_MID; i += 256) { sb1[i] = b1[i]; sb2[i] = b2[i]; }
    for (int i = threadIdx.x; i < C_MID * C_MID; i += 256) {
        int d = i / C_MID, c = i % C_MID;
        sW2T[i] = W2[c * C_MID + d];
    }
    __syncthreads();

    const int i = blockIdx.x * 256 + threadIdx.x;  // grid sized exactly
    float4 p = pts[i];

    int ix = (int)floorf((p.x + 50.0f) / 0.78125f);
    int iy = (int)floorf((p.y + 50.0f) / 0.78125f);
    bool valid = (ix >= 0) & (ix < BEV_W) & (iy >= 0) & (iy < BEV_H);

    int b = i / NP_;
    int g = b * HW_ + iy * BEV_W + ix;  // only used when valid

    // Layer 1: h = relu(p @ W1 + b1); pack pairs (h_c, h_{c+1})
    double h2[C_MID / 2];
#pragma unroll
    for (int c2 = 0; c2 < C_MID / 2; c2++) {
        int c = 2 * c2;
        float v0 = sb1[c], v1 = sb1[c + 1];
        v0 = fmaf(p.x, sW1[c], v0);             v1 = fmaf(p.x, sW1[c + 1], v1);
        v0 = fmaf(p.y, sW1[C_MID + c], v0);     v1 = fmaf(p.y, sW1[C_MID + c + 1], v1);
        v0 = fmaf(p.z, sW1[2 * C_MID + c], v0); v1 = fmaf(p.z, sW1[2 * C_MID + c + 1], v1);
        v0 = fmaf(p.w, sW1[3 * C_MID + c], v0); v1 = fmaf(p.w, sW1[3 * C_MID + c + 1], v1);
        h2[c2] = pack2(fmaxf(v0, 0.0f), fmaxf(v1, 0.0f));
    }

    // Layer 2: 4 output channels at a time, 8 independent FFMA2 chains.
    float* sums = &g_sums[(size_t)g * C_MID];
#pragma unroll 1
    for (int dg = 0; dg < C_MID; dg += 4) {
        double acc0a = 0.0, acc0b = 0.0, acc1a = 0.0, acc1b = 0.0;
        double acc2a = 0.0, acc2b = 0.0, acc3a = 0.0, acc3b = 0.0;
#pragma unroll
        for (int c4 = 0; c4 < C_MID; c4 += 4) {
            const int c2 = c4 / 2;
            double2 w0 = *reinterpret_cast<const double2*>(&sW2T[(dg + 0) * C_MID + c4]);
            fma2(acc0a, h2[c2], w0.x);  fma2(acc0b, h2[c2 + 1], w0.y);
            double2 w1 = *reinterpret_cast<const double2*>(&sW2T[(dg + 1) * C_MID + c4]);
            fma2(acc1a, h2[c2], w1.x);  fma2(acc1b, h2[c2 + 1], w1.y);
            double2 w2 = *reinterpret_cast<const double2*>(&sW2T[(dg + 2) * C_MID + c4]);
            fma2(acc2a, h2[c2], w2.x);  fma2(acc2b, h2[c2 + 1], w2.y);
            double2 w3 = *reinterpret_cast<const double2*>(&sW2T[(dg + 3) * C_MID + c4]);
            fma2(acc3a, h2[c2], w3.x);  fma2(acc3b, h2[c2 + 1], w3.y);
        }
        float2 s0 = unpack2(add2(acc0a, acc0b));
        float2 s1 = unpack2(add2(acc1a, acc1b));
        float2 s2 = unpack2(add2(acc2a, acc2b));
        float2 s3 = unpack2(add2(acc3a, acc3b));
        float e0 = fmaxf(s0.x + s0.y + sb2[dg + 0], 0.0f);
        float e1 = fmaxf(s1.x + s1.y + sb2[dg + 1], 0.0f);
        float e2 = fmaxf(s2.x + s2.y + sb2[dg + 2], 0.0f);
        float e3 = fmaxf(s3.x + s3.y + sb2[dg + 3], 0.0f);
        if (valid) {
            asm volatile("red.global.add.v4.f32 [%0], {%1, %2, %3, %4};"
                         :: "l"(&sums[dg]), "f"(e0), "f"(e1), "f"(e2), "f"(e3)
                         : "memory");
        }
    }
    if (valid) atomicAdd(&g_cnt[g], 1.0f);
}

// ---------------------------------------------------------------------------
// Kernel 2: mean + 1x1 conv (80->128) + BN + relu, NCHW output.
// ---------------------------------------------------------------------------
#define SUM_PAD 81

__global__ __launch_bounds__(128)
void bev_kernel(const float* __restrict__ Wp, const float* __restrict__ bp,
                const float* __restrict__ gamma, const float* __restrict__ beta,
                const float* __restrict__ rmean, const float* __restrict__ rvar,
                float* __restrict__ out) {
    extern __shared__ float smem[];
    float* sWp    = smem;                          // 80*128
    float* sSum   = sWp + C_MID * C_OUT;           // 128*81
    float* sScale = sSum + 128 * SUM_PAD;          // 128
    float* sShift = sScale + C_OUT;                // 128

    const int tid = threadIdx.x;
    const int row = blockIdx.x;

    for (int i = tid; i < C_MID * C_OUT; i += 128) sWp[i] = Wp[i];
    if (tid < C_OUT) {
        float sc = gamma[tid] * rsqrtf(rvar[tid] + 1e-5f);
        sScale[tid] = sc;
        sShift[tid] = beta[tid] + (bp[tid] - rmean[tid]) * sc;
    }
    const size_t gbase = (size_t)row * 128 * C_MID;
    for (int i = tid; i < 128 * C_MID; i += 128) {
        int px = i / C_MID, c = i % C_MID;
        sSum[px * SUM_PAD + c] = g_sums[gbase + i];
    }
    __syncthreads();

    float cnt = g_cnt[row * 128 + tid];
    float inv = 1.0f / fmaxf(cnt, 1.0f);
    float m[C_MID];
#pragma unroll
    for (int c = 0; c < C_MID; c++) m[c] = sSum[tid * SUM_PAD + c] * inv;

    const int b = row / BEV_H;
    const int iy = row % BEV_H;
    float* outp = out + (size_t)b * C_OUT * HW_ + (size_t)iy * BEV_W + tid;

#pragma unroll 2
    for (int d = 0; d < C_OUT; d++) {
        float acc = 0.0f;
#pragma unroll
        for (int c = 0; c < C_MID; c++)
            acc = fmaf(m[c], sWp[c * C_OUT + d], acc);
        outp[(size_t)d * HW_] = fmaxf(fmaf(acc, sScale[d], sShift[d]), 0.0f);
    }
}

// ---------------------------------------------------------------------------
extern "C" void kernel_launch(void* const* d_in, const int* in_sizes, int n_in,
                              void* d_out, int out_size) {
    const float4* pts   = (const float4*)d_in[0];
    const float*  W1    = (const float*)d_in[1];
    const float*  b1    = (const float*)d_in[2];
    const float*  W2    = (const float*)d_in[3];
    const float*  b2    = (const float*)d_in[4];
    const float*  Wp    = (const float*)d_in[5];
    const float*  bp    = (const float*)d_in[6];
    const float*  gamma = (const float*)d_in[7];
    const float*  beta  = (const float*)d_in[8];
    const float*  rmean = (const float*)d_in[9];
    const float*  rvar  = (const float*)d_in[10];
    float* out = (float*)d_out;

    zero_kernel<<<2048, 256>>>();

    point_kernel<<<TOTAL_PTS / 256, 256>>>(pts, W1, b1, W2, b2);

    size_t smem = (C_MID * C_OUT + 128 * SUM_PAD + 2 * C_OUT) * sizeof(float);
    cudaFuncSetAttribute(bev_kernel, cudaFuncAttributeMaxDynamicSharedMemorySize, (int)smem);
    bev_kernel<<<B_ * BEV_H, 128, smem>>>(Wp, bp, gamma, beta, rmean, rvar, out);
}

// round 3
// speedup vs baseline: 1.3257x; 1.1449x over previous
#include <cuda_runtime.h>
#include <cstdint>

#define BEV_H 128
#define BEV_W 128
#define HW_ (BEV_H * BEV_W)
#define C_MID 80
#define C_OUT 128
#define B_ 4
#define NP_ 200000
#define TOTAL_PTS (B_ * NP_)

// Scratch (device globals are zero-initialized at module load; bev_kernel
// re-zeroes exactly what it consumes, so every graph replay sees zeros).
__device__ float g_sums[(size_t)B_ * HW_ * C_MID];  // ~21 MB
__device__ float g_cnt[B_ * HW_];

// ---------------------------------------------------------------------------
// Packed fp32x2 helpers (sm_103a)
// ---------------------------------------------------------------------------
__device__ __forceinline__ void fma2(double& acc, double a, double b) {
    asm("fma.rn.f32x2 %0, %1, %2, %3;" : "=d"(acc) : "d"(a), "d"(b), "d"(acc));
}
__device__ __forceinline__ double pack2(float lo, float hi) {
    double r;
    asm("mov.b64 %0, {%1, %2};" : "=d"(r) : "f"(lo), "f"(hi));
    return r;
}
__device__ __forceinline__ float2 unpack2(double a) {
    float lo, hi;
    asm("mov.b64 {%0, %1}, %2;" : "=f"(lo), "=f"(hi) : "d"(a));
    return make_float2(lo, hi);
}

// ---------------------------------------------------------------------------
// Kernel 1: per-point MLP + scatter. TWO points per thread so every W2 weight
// loaded from shared (LDS.128 broadcast) feeds 4 fma.rn.f32x2 (2 per point).
// ---------------------------------------------------------------------------
__global__ __launch_bounds__(128, 2)
void point_kernel(const float4* __restrict__ pts,
                  const float* __restrict__ W1, const float* __restrict__ b1,
                  const float* __restrict__ W2, const float* __restrict__ b2) {
    __shared__ float sW1[4 * C_MID];
    __shared__ float sb1[C_MID];
    __shared__ float sb2[C_MID];
    __shared__ __align__(16) float sW2T[C_MID * C_MID];  // [d][c]

    for (int i = threadIdx.x; i < 4 * C_MID; i += 128) sW1[i] = W1[i];
    for (int i = threadIdx.x; i < C_MID; i += 128) { sb1[i] = b1[i]; sb2[i] = b2[i]; }
    for (int i = threadIdx.x; i < C_MID * C_MID; i += 128) {
        int d = i / C_MID, c = i % C_MID;
        sW2T[i] = W2[c * C_MID + d];
    }
    __syncthreads();

    const int base = blockIdx.x * 256;
    const int iA = base + threadIdx.x;
    const int iB = iA + 128;
    float4 pA = pts[iA];
    float4 pB = pts[iB];

    int ixA = (int)floorf((pA.x + 50.0f) / 0.78125f);
    int iyA = (int)floorf((pA.y + 50.0f) / 0.78125f);
    int ixB = (int)floorf((pB.x + 50.0f) / 0.78125f);
    int iyB = (int)floorf((pB.y + 50.0f) / 0.78125f);
    bool validA = (ixA >= 0) & (ixA < BEV_W) & (iyA >= 0) & (iyA < BEV_H);
    bool validB = (ixB >= 0) & (ixB < BEV_W) & (iyB >= 0) & (iyB < BEV_H);
    int gA = (iA / NP_) * HW_ + iyA * BEV_W + ixA;
    int gB = (iB / NP_) * HW_ + iyB * BEV_W + ixB;
    float* sumsA = &g_sums[(size_t)gA * C_MID];
    float* sumsB = &g_sums[(size_t)gB * C_MID];

    // Layer 1 for both points; weight float2 loads reused across points.
    double h2A[C_MID / 2], h2B[C_MID / 2];
#pragma unroll
    for (int c2 = 0; c2 < C_MID / 2; c2++) {
        int c = 2 * c2;
        float2 w0 = *reinterpret_cast<const float2*>(&sW1[c]);
        float2 w1 = *reinterpret_cast<const float2*>(&sW1[C_MID + c]);
        float2 w2 = *reinterpret_cast<const float2*>(&sW1[2 * C_MID + c]);
        float2 w3 = *reinterpret_cast<const float2*>(&sW1[3 * C_MID + c]);
        float bb0 = sb1[c], bb1 = sb1[c + 1];

        float a0 = fmaf(pA.x, w0.x, bb0), a1 = fmaf(pA.x, w0.y, bb1);
        a0 = fmaf(pA.y, w1.x, a0);  a1 = fmaf(pA.y, w1.y, a1);
        a0 = fmaf(pA.z, w2.x, a0);  a1 = fmaf(pA.z, w2.y, a1);
        a0 = fmaf(pA.w, w3.x, a0);  a1 = fmaf(pA.w, w3.y, a1);
        h2A[c2] = pack2(fmaxf(a0, 0.0f), fmaxf(a1, 0.0f));

        float b0 = fmaf(pB.x, w0.x, bb0), b1v = fmaf(pB.x, w0.y, bb1);
        b0 = fmaf(pB.y, w1.x, b0);  b1v = fmaf(pB.y, w1.y, b1v);
        b0 = fmaf(pB.z, w2.x, b0);  b1v = fmaf(pB.z, w2.y, b1v);
        b0 = fmaf(pB.w, w3.x, b0);  b1v = fmaf(pB.w, w3.y, b1v);
        h2B[c2] = pack2(fmaxf(b0, 0.0f), fmaxf(b1v, 0.0f));
    }

    // Layer 2: 4 output channels per iteration, both points share weight loads.
#pragma unroll 1
    for (int dg = 0; dg < C_MID; dg += 4) {
        double a0A = 0.0, a1A = 0.0, a2A = 0.0, a3A = 0.0;
        double a0B = 0.0, a1B = 0.0, a2B = 0.0, a3B = 0.0;
#pragma unroll
        for (int c4 = 0; c4 < C_MID; c4 += 4) {
            const int c2 = c4 / 2;
            double2 w0 = *reinterpret_cast<const double2*>(&sW2T[(dg + 0) * C_MID + c4]);
            fma2(a0A, h2A[c2], w0.x); fma2(a0A, h2A[c2 + 1], w0.y);
            fma2(a0B, h2B[c2], w0.x); fma2(a0B, h2B[c2 + 1], w0.y);
            double2 w1 = *reinterpret_cast<const double2*>(&sW2T[(dg + 1) * C_MID + c4]);
            fma2(a1A, h2A[c2], w1.x); fma2(a1A, h2A[c2 + 1], w1.y);
            fma2(a1B, h2B[c2], w1.x); fma2(a1B, h2B[c2 + 1], w1.y);
            double2 w2 = *reinterpret_cast<const double2*>(&sW2T[(dg + 2) * C_MID + c4]);
            fma2(a2A, h2A[c2], w2.x); fma2(a2A, h2A[c2 + 1], w2.y);
            fma2(a2B, h2B[c2], w2.x); fma2(a2B, h2B[c2 + 1], w2.y);
            double2 w3 = *reinterpret_cast<const double2*>(&sW2T[(dg + 3) * C_MID + c4]);
            fma2(a3A, h2A[c2], w3.x); fma2(a3A, h2A[c2 + 1], w3.y);
            fma2(a3B, h2B[c2], w3.x); fma2(a3B, h2B[c2 + 1], w3.y);
        }
        float bi0 = sb2[dg + 0], bi1 = sb2[dg + 1], bi2 = sb2[dg + 2], bi3 = sb2[dg + 3];
        float2 s0 = unpack2(a0A), s1 = unpack2(a1A), s2 = unpack2(a2A), s3 = unpack2(a3A);
        float e0 = fmaxf(s0.x + s0.y + bi0, 0.0f);
        float e1 = fmaxf(s1.x + s1.y + bi1, 0.0f);
        float e2 = fmaxf(s2.x + s2.y + bi2, 0.0f);
        float e3 = fmaxf(s3.x + s3.y + bi3, 0.0f);
        if (validA) {
            asm volatile("red.global.add.v4.f32 [%0], {%1, %2, %3, %4};"
                         :: "l"(&sumsA[dg]), "f"(e0), "f"(e1), "f"(e2), "f"(e3) : "memory");
        }
        s0 = unpack2(a0B); s1 = unpack2(a1B); s2 = unpack2(a2B); s3 = unpack2(a3B);
        e0 = fmaxf(s0.x + s0.y + bi0, 0.0f);
        e1 = fmaxf(s1.x + s1.y + bi1, 0.0f);
        e2 = fmaxf(s2.x + s2.y + bi2, 0.0f);
        e3 = fmaxf(s3.x + s3.y + bi3, 0.0f);
        if (validB) {
            asm volatile("red.global.add.v4.f32 [%0], {%1, %2, %3, %4};"
                         :: "l"(&sumsB[dg]), "f"(e0), "f"(e1), "f"(e2), "f"(e3) : "memory");
        }
    }
    if (validA) atomicAdd(&g_cnt[gA], 1.0f);
    if (validB) atomicAdd(&g_cnt[gB], 1.0f);
}

// ---------------------------------------------------------------------------
// Kernel 2: mean + 1x1 conv (80->128, f32x2) + BN + relu, NCHW out.
// Also re-zeroes exactly the g_sums/g_cnt elements it consumed.
// ---------------------------------------------------------------------------
#define SUM_PAD 82  // even stride so double2-aligned pairs work; 82*4B

__global__ __launch_bounds__(128)
void bev_kernel(const float* __restrict__ Wp, const float* __restrict__ bp,
                const float* __restrict__ gamma, const float* __restrict__ beta,
                const float* __restrict__ rmean, const float* __restrict__ rvar,
                float* __restrict__ out) {
    extern __shared__ float smem[];
    float* sWpT   = smem;                          // [d][c] 128*80
    float* sSum   = sWpT + C_OUT * C_MID;          // 128*82
    float* sScale = sSum + 128 * SUM_PAD;          // 128
    float* sShift = sScale + C_OUT;                // 128

    const int tid = threadIdx.x;
    const int row = blockIdx.x;

    for (int i = tid; i < C_MID * C_OUT; i += 128) {
        int d = i / C_MID, c = i % C_MID;
        sWpT[i] = Wp[c * C_OUT + d];
    }
    if (tid < C_OUT) {
        float sc = gamma[tid] * rsqrtf(rvar[tid] + 1e-5f);
        sScale[tid] = sc;
        sShift[tid] = beta[tid] + (bp[tid] - rmean[tid]) * sc;
    }
    // Stage this row's sums (coalesced), zeroing behind the reads.
    const size_t gbase = (size_t)row * 128 * C_MID;
    for (int i = tid; i < 128 * C_MID; i += 128) {
        int px = i / C_MID, c = i % C_MID;
        float v = g_sums[gbase + i];
        g_sums[gbase + i] = 0.0f;
        sSum[px * SUM_PAD + c] = v;
    }
    __syncthreads();

    float cnt = g_cnt[row * 128 + tid];
    g_cnt[row * 128 + tid] = 0.0f;
    float inv = 1.0f / fmaxf(cnt, 1.0f);

    double m2[C_MID / 2];
#pragma unroll
    for (int c2 = 0; c2 < C_MID / 2; c2++) {
        float2 s = *reinterpret_cast<const float2*>(&sSum[tid * SUM_PAD + 2 * c2]);
        m2[c2] = pack2(s.x * inv, s.y * inv);
    }

    const int b = row / BEV_H;
    const int iy = row % BEV_H;
    float* outp = out + (size_t)b * C_OUT * HW_ + (size_t)iy * BEV_W + tid;

#pragma unroll 2
    for (int d = 0; d < C_OUT; d++) {
        double acc0 = 0.0, acc1 = 0.0;
#pragma unroll
        for (int c4 = 0; c4 < C_MID; c4 += 4) {
            double2 w = *reinterpret_cast<const double2*>(&sWpT[d * C_MID + c4]);
            fma2(acc0, m2[c4 / 2], w.x);
            fma2(acc1, m2[c4 / 2 + 1], w.y);
        }
        float2 s0 = unpack2(acc0), s1 = unpack2(acc1);
        float v = (s0.x + s0.y) + (s1.x + s1.y);
        outp[(size_t)d * HW_] = fmaxf(fmaf(v, sScale[d], sShift[d]), 0.0f);
    }
}

// Tiny trailing kernel so ncu's skip-5 lands on point_kernel next round.
__global__ void probe_kernel() {}

// ---------------------------------------------------------------------------
extern "C" void kernel_launch(void* const* d_in, const int* in_sizes, int n_in,
                              void* d_out, int out_size) {
    const float4* pts   = (const float4*)d_in[0];
    const float*  W1    = (const float*)d_in[1];
    const float*  b1    = (const float*)d_in[2];
    const float*  W2    = (const float*)d_in[3];
    const float*  b2    = (const float*)d_in[4];
    const float*  Wp    = (const float*)d_in[5];
    const float*  bp    = (const float*)d_in[6];
    const float*  gamma = (const float*)d_in[7];
    const float*  beta  = (const float*)d_in[8];
    const float*  rmean = (const float*)d_in[9];
    const float*  rvar  = (const float*)d_in[10];
    float* out = (float*)d_out;

    point_kernel<<<TOTAL_PTS / 256, 128>>>(pts, W1, b1, W2, b2);

    size_t smem = (C_OUT * C_MID + 128 * SUM_PAD + 2 * C_OUT) * sizeof(float);
    cudaFuncSetAttribute(bev_kernel, cudaFuncAttributeMaxDynamicSharedMemorySize, (int)smem);
    bev_kernel<<<B_ * BEV_H, 128, smem>>>(Wp, bp, gamma, beta, rmean, rvar, out);

    probe_kernel<<<1, 1>>>();
}

// round 5
// speedup vs baseline: 2.8380x; 2.1408x over previous
#include <cuda_runtime.h>
#include <cstdint>

#define BEV_H 128
#define BEV_W 128
#define HW_ (BEV_H * BEV_W)
#define C_MID 80
#define C_OUT 128
#define B_ 4
#define NP_ 200000
#define TOTAL_PTS (B_ * NP_)

// point kernel geometry: 128 threads = 4 warps, each warp 5 tiles of 32 points
#define WARPS_PER_CTA 4
#define TILES_PER_WARP 5
#define POINT_GRID (TOTAL_PTS / (32 * WARPS_PER_CTA * TILES_PER_WARP))  // 1250

// Scratch (zero-init at load; bev_kernel re-zeroes what it consumes).
__device__ float g_sums[(size_t)B_ * HW_ * C_MID];  // ~21 MB
__device__ float g_cnt[B_ * HW_];

// ---------------------------------------------------------------------------
// helpers
// ---------------------------------------------------------------------------
__device__ __forceinline__ uint32_t f2tf32(float x) {
    uint32_t u;
    asm("cvt.rna.tf32.f32 %0, %1;" : "=r"(u) : "f"(x));
    return u;
}
__device__ __forceinline__ void fma2(double& acc, double a, double b) {
    asm("fma.rn.f32x2 %0, %1, %2, %3;" : "=d"(acc) : "d"(a), "d"(b), "d"(acc));
}
__device__ __forceinline__ double pack2(float lo, float hi) {
    double r; asm("mov.b64 %0, {%1, %2};" : "=d"(r) : "f"(lo), "f"(hi)); return r;
}
__device__ __forceinline__ float2 unpack2(double a) {
    float lo, hi; asm("mov.b64 {%0, %1}, %2;" : "=f"(lo), "=f"(hi) : "d"(a));
    return make_float2(lo, hi);
}
// m16n8k8 row.col f32.tf32.tf32.f32
__device__ __forceinline__ void mma_tf32(float* c, const uint32_t* a,
                                         uint32_t b0, uint32_t b1) {
    asm("mma.sync.aligned.m16n8k8.row.col.f32.tf32.tf32.f32 "
        "{%0,%1,%2,%3}, {%4,%5,%6,%7}, {%8,%9}, {%0,%1,%2,%3};"
        : "+f"(c[0]), "+f"(c[1]), "+f"(c[2]), "+f"(c[3])
        : "r"(a[0]), "r"(a[1]), "r"(a[2]), "r"(a[3]), "r"(b0), "r"(b1));
}

// ---------------------------------------------------------------------------
// Kernel 1: per-point MLP via legacy tensor cores.
// Warp tile = 32 points. A = h (32x80 tf32, fragments built in registers
// straight out of layer-1). B = W2 (80x80) pre-staged in shared in exact
// b-fragment order. C scattered with red.global.add.v4.f32 after a 4-shuffle
// lane exchange that assembles 4 consecutive channels per thread.
// ---------------------------------------------------------------------------
__global__ __launch_bounds__(128)
void point_mma_kernel(const float4* __restrict__ pts,
                      const float* __restrict__ W1, const float* __restrict__ b1,
                      const float* __restrict__ W2, const float* __restrict__ b2) {
    __shared__ uint32_t sW2F[10 * 10 * 32 * 2];  // b-frag order, 25.6 KB
    __shared__ float sW1[4 * C_MID];
    __shared__ float sb1[C_MID];
    __shared__ __align__(16) float sb2[C_MID];
    __shared__ int g_buf[WARPS_PER_CTA][32];

    const int tid = threadIdx.x;
    const int w = tid >> 5;
    const int lane = tid & 31;
    const int qg = lane >> 2;    // groupID
    const int tig = lane & 3;    // thread-in-group

    for (int i = tid; i < 4 * C_MID; i += 128) sW1[i] = W1[i];
    for (int i = tid; i < C_MID; i += 128) { sb1[i] = b1[i]; sb2[i] = b2[i]; }
    // B fragments: b0 = W2[k=8ks+tig][n=8ns+qg], b1 = W2[k=8ks+tig+4][n]
    for (int e = tid; e < 6400; e += 128) {
        int pair = e & 1;
        int L = (e >> 1) & 31;
        int idx = e >> 6;            // ks*10+ns
        int ns = idx % 10, ks = idx / 10;
        int k = ks * 8 + (L & 3) + pair * 4;
        int n = ns * 8 + (L >> 2);
        sW2F[e] = f2tf32(W2[k * C_MID + n]);
    }
    __syncthreads();

    const bool even = (tig & 1) == 0;

    for (int t = 0; t < TILES_PER_WARP; t++) {
        const int tile = (blockIdx.x * WARPS_PER_CTA + w) * TILES_PER_WARP + t;
        const int base = tile * 32;

        // Load the 4 point rows this thread's fragments need: rows qg + 8j.
        float4 P[4];
#pragma unroll
        for (int j = 0; j < 4; j++) P[j] = pts[base + qg + 8 * j];

        // This thread owns point row qg + 8*tig for bucket bookkeeping.
        {
            float4 po = P[tig];
            int ixo = (int)floorf((po.x + 50.0f) / 0.78125f);
            int iyo = (int)floorf((po.y + 50.0f) / 0.78125f);
            bool v = (ixo >= 0) & (ixo < BEV_W) & (iyo >= 0) & (iyo < BEV_H);
            int row = qg + 8 * tig;
            int gb = v ? ((base + row) / NP_) * HW_ + iyo * BEV_W + ixo : -1;
            g_buf[w][row] = gb;
            if (v) atomicAdd(&g_cnt[gb], 1.0f);
        }
        __syncwarp();

        // Layer 1 straight into A fragments.
        // A[t][ks] = { h[qg+16t][c0], h[qg+16t+8][c0], h[qg+16t][c1], h[qg+16t+8][c1] }
        uint32_t A0[10][4], A1[10][4];
#pragma unroll
        for (int ks = 0; ks < 10; ks++) {
            const int c0 = ks * 8 + tig, c1 = c0 + 4;
            float w00 = sW1[c0], w01 = sW1[C_MID + c0],
                  w02 = sW1[2 * C_MID + c0], w03 = sW1[3 * C_MID + c0], bb0 = sb1[c0];
            float w10 = sW1[c1], w11 = sW1[C_MID + c1],
                  w12 = sW1[2 * C_MID + c1], w13 = sW1[3 * C_MID + c1], bb1 = sb1[c1];
#pragma unroll
            for (int j = 0; j < 4; j++) {
                float v0 = fmaf(P[j].x, w00, bb0);
                v0 = fmaf(P[j].y, w01, v0);
                v0 = fmaf(P[j].z, w02, v0);
                v0 = fmaf(P[j].w, w03, v0);
                float v1 = fmaf(P[j].x, w10, bb1);
                v1 = fmaf(P[j].y, w11, v1);
                v1 = fmaf(P[j].z, w12, v1);
                v1 = fmaf(P[j].w, w13, v1);
                uint32_t u0 = f2tf32(fmaxf(v0, 0.0f));
                uint32_t u1 = f2tf32(fmaxf(v1, 0.0f));
                if (j < 2) { A0[ks][j] = u0; A0[ks][2 + j] = u1; }
                else       { A1[ks][j - 2] = u0; A1[ks][j] = u1; }
            }
        }

        // Rows this thread scatters in the epilogue.
        const int row0 = (even ? qg : qg + 16);
        const int row1 = row0 + 8;
        const int gv0 = g_buf[w][row0];
        const int gv1 = g_buf[w][row1];

#pragma unroll 1
        for (int ns = 0; ns < 10; ns++) {
            float c0[4] = {0.f, 0.f, 0.f, 0.f};
            float c1[4] = {0.f, 0.f, 0.f, 0.f};
#pragma unroll
            for (int ks = 0; ks < 10; ks++) {
                uint2 bf = *reinterpret_cast<const uint2*>(
                    &sW2F[((ks * 10 + ns) * 32 + lane) * 2]);
                mma_tf32(c0, A0[ks], bf.x, bf.y);
                mma_tf32(c1, A1[ks], bf.x, bf.y);
            }
            // Exchange: even lane keeps tile0, sends tile1; odd the reverse.
            float r0 = __shfl_xor_sync(0xffffffffu, even ? c1[0] : c0[0], 1);
            float r1 = __shfl_xor_sync(0xffffffffu, even ? c1[1] : c0[1], 1);
            float r2 = __shfl_xor_sync(0xffffffffu, even ? c1[2] : c0[2], 1);
            float r3 = __shfl_xor_sync(0xffffffffu, even ? c1[3] : c0[3], 1);
            float k0 = even ? c0[0] : c1[0], k1 = even ? c0[1] : c1[1];
            float k2 = even ? c0[2] : c1[2], k3 = even ? c0[3] : c1[3];
            // row0 channels colbase..+3 ; row1 same cols
            float x0 = even ? k0 : r0, x1 = even ? k1 : r1;
            float x2 = even ? r0 : k0, x3 = even ? r1 : k1;
            float y0 = even ? k2 : r2, y1 = even ? k3 : r3;
            float y2 = even ? r2 : k2, y3 = even ? r3 : k3;
            const int colbase = ns * 8 + (even ? 2 * tig : 2 * tig - 2);
            float4 bb = *reinterpret_cast<const float4*>(&sb2[colbase]);
            float e0 = fmaxf(x0 + bb.x, 0.0f), e1 = fmaxf(x1 + bb.y, 0.0f);
            float e2 = fmaxf(x2 + bb.z, 0.0f), e3 = fmaxf(x3 + bb.w, 0.0f);
            float f0 = fmaxf(y0 + bb.x, 0.0f), f1 = fmaxf(y1 + bb.y, 0.0f);
            float f2v = fmaxf(y2 + bb.z, 0.0f), f3 = fmaxf(y3 + bb.w, 0.0f);
            if (gv0 >= 0) {
                asm volatile("red.global.add.v4.f32 [%0], {%1, %2, %3, %4};"
                             :: "l"(&g_sums[(size_t)gv0 * C_MID + colbase]),
                                "f"(e0), "f"(e1), "f"(e2), "f"(e3) : "memory");
            }
            if (gv1 >= 0) {
                asm volatile("red.global.add.v4.f32 [%0], {%1, %2, %3, %4};"
                             :: "l"(&g_sums[(size_t)gv1 * C_MID + colbase]),
                                "f"(f0), "f"(f1), "f"(f2v), "f"(f3) : "memory");
            }
        }
        __syncwarp();
    }
}

// ---------------------------------------------------------------------------
// Kernel 2: mean + 1x1 conv (80->128, f32x2) + BN + relu, NCHW out.
// g_sums loaded straight to registers (zeroed behind); only WpT in shared
// so occupancy doubles vs the previous version.
// ---------------------------------------------------------------------------
__global__ __launch_bounds__(128)
void bev_kernel(const float* __restrict__ Wp, const float* __restrict__ bp,
                const float* __restrict__ gamma, const float* __restrict__ beta,
                const float* __restrict__ rmean, const float* __restrict__ rvar,
                float* __restrict__ out) {
    __shared__ __align__(16) float sWpT[C_OUT * C_MID];  // [d][c], 40 KB
    __shared__ float sScale[C_OUT];
    __shared__ float sShift[C_OUT];

    const int tid = threadIdx.x;
    const int row = blockIdx.x;

    for (int i = tid; i < C_MID * C_OUT; i += 128) {
        int d = i / C_MID, c = i % C_MID;
        sWpT[i] = Wp[c * C_OUT + d];
    }
    if (tid < C_OUT) {
        float sc = gamma[tid] * rsqrtf(rvar[tid] + 1e-5f);
        sScale[tid] = sc;
        sShift[tid] = beta[tid] + (bp[tid] - rmean[tid]) * sc;
    }

    const int bucket = row * 128 + tid;
    float cnt = g_cnt[bucket];
    g_cnt[bucket] = 0.0f;
    float inv = 1.0f / fmaxf(cnt, 1.0f);

    // Load this pixel's 80 sums directly, zero behind the read.
    float4* src = reinterpret_cast<float4*>(&g_sums[(size_t)bucket * C_MID]);
    double m2[C_MID / 2];
#pragma unroll
    for (int q = 0; q < C_MID / 4; q++) {
        float4 v = src[q];
        src[q] = make_float4(0.f, 0.f, 0.f, 0.f);
        m2[2 * q]     = pack2(v.x * inv, v.y * inv);
        m2[2 * q + 1] = pack2(v.z * inv, v.w * inv);
    }
    __syncthreads();

    const int b = row / BEV_H;
    const int iy = row % BEV_H;
    float* outp = out + (size_t)b * C_OUT * HW_ + (size_t)iy * BEV_W + tid;

#pragma unroll 2
    for (int d = 0; d < C_OUT; d++) {
        double acc0 = 0.0, acc1 = 0.0;
#pragma unroll
        for (int c4 = 0; c4 < C_MID; c4 += 4) {
            double2 wv = *reinterpret_cast<const double2*>(&sWpT[d * C_MID + c4]);
            fma2(acc0, m2[c4 / 2], wv.x);
            fma2(acc1, m2[c4 / 2 + 1], wv.y);
        }
        float2 s0 = unpack2(acc0), s1 = unpack2(acc1);
        float v = (s0.x + s0.y) + (s1.x + s1.y);
        outp[(size_t)d * HW_] = fmaxf(fmaf(v, sScale[d], sShift[d]), 0.0f);
    }
}

__global__ void probe_kernel() {}

// ---------------------------------------------------------------------------
extern "C" void kernel_launch(void* const* d_in, const int* in_sizes, int n_in,
                              void* d_out, int out_size) {
    const float4* pts   = (const float4*)d_in[0];
    const float*  W1    = (const float*)d_in[1];
    const float*  b1    = (const float*)d_in[2];
    const float*  W2    = (const float*)d_in[3];
    const float*  b2    = (const float*)d_in[4];
    const float*  Wp    = (const float*)d_in[5];
    const float*  bp    = (const float*)d_in[6];
    const float*  gamma = (const float*)d_in[7];
    const float*  beta  = (const float*)d_in[8];
    const float*  rmean = (const float*)d_in[9];
    const float*  rvar  = (const float*)d_in[10];
    float* out = (float*)d_out;

    point_mma_kernel<<<POINT_GRID, 128>>>(pts, W1, b1, W2, b2);
    bev_kernel<<<B_ * BEV_H, 128>>>(Wp, bp, gamma, beta, rmean, rvar, out);
    probe_kernel<<<1, 1>>>();
}

// round 6
// speedup vs baseline: 3.9561x; 1.3940x over previous
#include <cuda_runtime.h>
#include <cstdint>

#define BEV_H 128
#define BEV_W 128
#define HW_ (BEV_H * BEV_W)
#define C_MID 80
#define C_OUT 128
#define B_ 4
#define NP_ 200000
#define TOTAL_PTS (B_ * NP_)

#define WARPS_PER_CTA 4
#define TILES_PER_WARP 5
#define POINT_GRID (TOTAL_PTS / (32 * WARPS_PER_CTA * TILES_PER_WARP))  // 1250

// bev mma geometry: 16 pixels per warp-tile, 4 tiles per warp, 4 warps/CTA
#define BEV_TILES (B_ * HW_ / 16)              // 4096
#define BEV_TPW 4
#define BEV_GRID (BEV_TILES / (4 * BEV_TPW))   // 256

// Scratch (zero-init at load; bev_kernel re-zeroes what it consumes).
__device__ float g_sums[(size_t)B_ * HW_ * C_MID];  // ~21 MB
__device__ float g_cnt[B_ * HW_];

// ---------------------------------------------------------------------------
// helpers
// ---------------------------------------------------------------------------
__device__ __forceinline__ uint32_t f2tf32(float x) {
    uint32_t u;
    asm("cvt.rna.tf32.f32 %0, %1;" : "=r"(u) : "f"(x));
    return u;
}
// m16n8k8 row.col f32.tf32.tf32.f32
__device__ __forceinline__ void mma_tf32(float* c, const uint32_t* a,
                                         uint32_t b0, uint32_t b1) {
    asm("mma.sync.aligned.m16n8k8.row.col.f32.tf32.tf32.f32 "
        "{%0,%1,%2,%3}, {%4,%5,%6,%7}, {%8,%9}, {%0,%1,%2,%3};"
        : "+f"(c[0]), "+f"(c[1]), "+f"(c[2]), "+f"(c[3])
        : "r"(a[0]), "r"(a[1]), "r"(a[2]), "r"(a[3]), "r"(b0), "r"(b1));
}

// ---------------------------------------------------------------------------
// Kernel 1: per-point MLP via tensor cores (unchanged from R5; 103 us).
// ---------------------------------------------------------------------------
__global__ __launch_bounds__(128)
void point_mma_kernel(const float4* __restrict__ pts,
                      const float* __restrict__ W1, const float* __restrict__ b1,
                      const float* __restrict__ W2, const float* __restrict__ b2) {
    __shared__ uint32_t sW2F[10 * 10 * 32 * 2];  // b-frag order, 25.6 KB
    __shared__ float sW1[4 * C_MID];
    __shared__ float sb1[C_MID];
    __shared__ __align__(16) float sb2[C_MID];
    __shared__ int g_buf[WARPS_PER_CTA][32];

    const int tid = threadIdx.x;
    const int w = tid >> 5;
    const int lane = tid & 31;
    const int qg = lane >> 2;
    const int tig = lane & 3;

    for (int i = tid; i < 4 * C_MID; i += 128) sW1[i] = W1[i];
    for (int i = tid; i < C_MID; i += 128) { sb1[i] = b1[i]; sb2[i] = b2[i]; }
    for (int e = tid; e < 6400; e += 128) {
        int pair = e & 1;
        int L = (e >> 1) & 31;
        int idx = e >> 6;
        int ns = idx % 10, ks = idx / 10;
        int k = ks * 8 + (L & 3) + pair * 4;
        int n = ns * 8 + (L >> 2);
        sW2F[e] = f2tf32(W2[k * C_MID + n]);
    }
    __syncthreads();

    const bool even = (tig & 1) == 0;

    for (int t = 0; t < TILES_PER_WARP; t++) {
        const int tile = (blockIdx.x * WARPS_PER_CTA + w) * TILES_PER_WARP + t;
        const int base = tile * 32;

        float4 P[4];
#pragma unroll
        for (int j = 0; j < 4; j++) P[j] = pts[base + qg + 8 * j];

        {
            float4 po = P[tig];
            int ixo = (int)floorf((po.x + 50.0f) / 0.78125f);
            int iyo = (int)floorf((po.y + 50.0f) / 0.78125f);
            bool v = (ixo >= 0) & (ixo < BEV_W) & (iyo >= 0) & (iyo < BEV_H);
            int row = qg + 8 * tig;
            int gb = v ? ((base + row) / NP_) * HW_ + iyo * BEV_W + ixo : -1;
            g_buf[w][row] = gb;
            if (v) atomicAdd(&g_cnt[gb], 1.0f);
        }
        __syncwarp();

        uint32_t A0[10][4], A1[10][4];
#pragma unroll
        for (int ks = 0; ks < 10; ks++) {
            const int c0 = ks * 8 + tig, c1 = c0 + 4;
            float w00 = sW1[c0], w01 = sW1[C_MID + c0],
                  w02 = sW1[2 * C_MID + c0], w03 = sW1[3 * C_MID + c0], bb0 = sb1[c0];
            float w10 = sW1[c1], w11 = sW1[C_MID + c1],
                  w12 = sW1[2 * C_MID + c1], w13 = sW1[3 * C_MID + c1], bb1 = sb1[c1];
#pragma unroll
            for (int j = 0; j < 4; j++) {
                float v0 = fmaf(P[j].x, w00, bb0);
                v0 = fmaf(P[j].y, w01, v0);
                v0 = fmaf(P[j].z, w02, v0);
                v0 = fmaf(P[j].w, w03, v0);
                float v1 = fmaf(P[j].x, w10, bb1);
                v1 = fmaf(P[j].y, w11, v1);
                v1 = fmaf(P[j].z, w12, v1);
                v1 = fmaf(P[j].w, w13, v1);
                uint32_t u0 = f2tf32(fmaxf(v0, 0.0f));
                uint32_t u1 = f2tf32(fmaxf(v1, 0.0f));
                if (j < 2) { A0[ks][j] = u0; A0[ks][2 + j] = u1; }
                else       { A1[ks][j - 2] = u0; A1[ks][j] = u1; }
            }
        }

        const int row0 = (even ? qg : qg + 16);
        const int row1 = row0 + 8;
        const int gv0 = g_buf[w][row0];
        const int gv1 = g_buf[w][row1];

#pragma unroll 1
        for (int ns = 0; ns < 10; ns++) {
            float c0[4] = {0.f, 0.f, 0.f, 0.f};
            float c1[4] = {0.f, 0.f, 0.f, 0.f};
#pragma unroll
            for (int ks = 0; ks < 10; ks++) {
                uint2 bf = *reinterpret_cast<const uint2*>(
                    &sW2F[((ks * 10 + ns) * 32 + lane) * 2]);
                mma_tf32(c0, A0[ks], bf.x, bf.y);
                mma_tf32(c1, A1[ks], bf.x, bf.y);
            }
            float r0 = __shfl_xor_sync(0xffffffffu, even ? c1[0] : c0[0], 1);
            float r1 = __shfl_xor_sync(0xffffffffu, even ? c1[1] : c0[1], 1);
            float r2 = __shfl_xor_sync(0xffffffffu, even ? c1[2] : c0[2], 1);
            float r3 = __shfl_xor_sync(0xffffffffu, even ? c1[3] : c0[3], 1);
            float k0 = even ? c0[0] : c1[0], k1 = even ? c0[1] : c1[1];
            float k2 = even ? c0[2] : c1[2], k3 = even ? c0[3] : c1[3];
            float x0 = even ? k0 : r0, x1 = even ? k1 : r1;
            float x2 = even ? r0 : k0, x3 = even ? r1 : k1;
            float y0 = even ? k2 : r2, y1 = even ? k3 : r3;
            float y2 = even ? r2 : k2, y3 = even ? r3 : k3;
            const int colbase = ns * 8 + (even ? 2 * tig : 2 * tig - 2);
            float4 bb = *reinterpret_cast<const float4*>(&sb2[colbase]);
            float e0 = fmaxf(x0 + bb.x, 0.0f), e1 = fmaxf(x1 + bb.y, 0.0f);
            float e2 = fmaxf(x2 + bb.z, 0.0f), e3 = fmaxf(x3 + bb.w, 0.0f);
            float f0 = fmaxf(y0 + bb.x, 0.0f), f1 = fmaxf(y1 + bb.y, 0.0f);
            float f2v = fmaxf(y2 + bb.z, 0.0f), f3 = fmaxf(y3 + bb.w, 0.0f);
            if (gv0 >= 0) {
                asm volatile("red.global.add.v4.f32 [%0], {%1, %2, %3, %4};"
                             :: "l"(&g_sums[(size_t)gv0 * C_MID + colbase]),
                                "f"(e0), "f"(e1), "f"(e2), "f"(e3) : "memory");
            }
            if (gv1 >= 0) {
                asm volatile("red.global.add.v4.f32 [%0], {%1, %2, %3, %4};"
                             :: "l"(&g_sums[(size_t)gv1 * C_MID + colbase]),
                                "f"(f0), "f"(f1), "f"(f2v), "f"(f3) : "memory");
            }
        }
        __syncwarp();
    }
}

// ---------------------------------------------------------------------------
// Kernel 2: mean + 1x1 conv + BN + relu via tensor cores.
// Warp tile = 16 consecutive pixels. A = means (16x80 tf32 from g_sums/cnt),
// B = Wp (80x128) staged in b-fragment order. BN folded into scale/shift.
// Zeroes g_sums/g_cnt behind the reads (tiles are warp-private).
// ---------------------------------------------------------------------------
__global__ __launch_bounds__(128)
void bev_mma_kernel(const float* __restrict__ Wp, const float* __restrict__ bp,
                    const float* __restrict__ gamma, const float* __restrict__ beta,
                    const float* __restrict__ rmean, const float* __restrict__ rvar,
                    float* __restrict__ out) {
    __shared__ uint32_t sWpF[10 * 16 * 32 * 2];  // 40 KB, b-frag order
    __shared__ float sScale[C_OUT];
    __shared__ float sShift[C_OUT];

    const int tid = threadIdx.x;
    const int w = tid >> 5;
    const int lane = tid & 31;
    const int qg = lane >> 2;
    const int tig = lane & 3;

    // b0 = Wp[k=8ks+tig][n=8ns+qg], b1 = Wp[k+4][n]  (Wp row-major (c,d))
    for (int e = tid; e < 10240; e += 128) {
        int pair = e & 1;
        int L = (e >> 1) & 31;
        int idx = e >> 6;             // ks*16+ns
        int ns = idx & 15, ks = idx >> 4;
        int k = ks * 8 + (L & 3) + pair * 4;
        int n = ns * 8 + (L >> 2);
        sWpF[e] = f2tf32(Wp[k * C_OUT + n]);
    }
    if (tid < C_OUT) {
        float sc = gamma[tid] * rsqrtf(rvar[tid] + 1e-5f);
        sScale[tid] = sc;
        sShift[tid] = beta[tid] + (bp[tid] - rmean[tid]) * sc;
    }
    __syncthreads();

#pragma unroll 1
    for (int t = 0; t < BEV_TPW; t++) {
        const int tile = (blockIdx.x * 4 + w) * BEV_TPW + t;
        const int tb = tile * 16;   // 16 consecutive pixels within one BEV row

        // Means for rows qg and qg+8 of this tile.
        float cnt0 = g_cnt[tb + qg];
        float cnt1 = g_cnt[tb + qg + 8];
        float inv0 = 1.0f / fmaxf(cnt0, 1.0f);
        float inv1 = 1.0f / fmaxf(cnt1, 1.0f);
        const float* p0 = &g_sums[(size_t)(tb + qg) * C_MID];
        const float* p1 = &g_sums[(size_t)(tb + qg + 8) * C_MID];

        uint32_t A[10][4];
#pragma unroll
        for (int ks = 0; ks < 10; ks++) {
            const int c0 = ks * 8 + tig, c1 = c0 + 4;
            A[ks][0] = f2tf32(p0[c0] * inv0);
            A[ks][1] = f2tf32(p1[c0] * inv1);
            A[ks][2] = f2tf32(p0[c1] * inv0);
            A[ks][3] = f2tf32(p1[c1] * inv1);
        }
        __syncwarp();
        // Zero behind the reads (coalesced float4; warp-private region).
        float4* zs = reinterpret_cast<float4*>(&g_sums[(size_t)tb * C_MID]);
#pragma unroll
        for (int j = 0; j < 10; j++)
            zs[lane + 32 * j] = make_float4(0.f, 0.f, 0.f, 0.f);
        if (lane < 16) g_cnt[tb + lane] = 0.0f;

        // Output base: tile is 16 px along x in row (b, iy).
        const int b = tb / HW_;
        const int rem = tb % HW_;
        float* outb = out + (size_t)b * C_OUT * HW_ + rem;  // + col*HW_ + row

#pragma unroll 1
        for (int ns = 0; ns < 16; ns++) {
            float c[4] = {0.f, 0.f, 0.f, 0.f};
#pragma unroll
            for (int ks = 0; ks < 10; ks++) {
                uint2 bf = *reinterpret_cast<const uint2*>(
                    &sWpF[((ks * 16 + ns) * 32 + lane) * 2]);
                mma_tf32(c, A[ks], bf.x, bf.y);
            }
            // D[qg][col0], D[qg][col1], D[qg+8][col0], D[qg+8][col1]
            const int col0 = ns * 8 + 2 * tig;
            float2 sc = *reinterpret_cast<const float2*>(&sScale[col0]);
            float2 sh = *reinterpret_cast<const float2*>(&sShift[col0]);
            float v00 = fmaxf(fmaf(c[0], sc.x, sh.x), 0.0f);
            float v01 = fmaxf(fmaf(c[1], sc.y, sh.y), 0.0f);
            float v10 = fmaxf(fmaf(c[2], sc.x, sh.x), 0.0f);
            float v11 = fmaxf(fmaf(c[3], sc.y, sh.y), 0.0f);
            outb[(size_t)col0 * HW_ + qg] = v00;
            outb[(size_t)(col0 + 1) * HW_ + qg] = v01;
            outb[(size_t)col0 * HW_ + qg + 8] = v10;
            outb[(size_t)(col0 + 1) * HW_ + qg + 8] = v11;
        }
        __syncwarp();
    }
}

__global__ void probe_kernel() {}

// ---------------------------------------------------------------------------
extern "C" void kernel_launch(void* const* d_in, const int* in_sizes, int n_in,
                              void* d_out, int out_size) {
    const float4* pts   = (const float4*)d_in[0];
    const float*  W1    = (const float*)d_in[1];
    const float*  b1    = (const float*)d_in[2];
    const float*  W2    = (const float*)d_in[3];
    const float*  b2    = (const float*)d_in[4];
    const float*  Wp    = (const float*)d_in[5];
    const float*  bp    = (const float*)d_in[6];
    const float*  gamma = (const float*)d_in[7];
    const float*  beta  = (const float*)d_in[8];
    const float*  rmean = (const float*)d_in[9];
    const float*  rvar  = (const float*)d_in[10];
    float* out = (float*)d_out;

    point_mma_kernel<<<POINT_GRID, 128>>>(pts, W1, b1, W2, b2);
    bev_mma_kernel<<<BEV_GRID, 128>>>(Wp, bp, gamma, beta, rmean, rvar, out);
    probe_kernel<<<1, 1>>>();
}